// round 1
// baseline (speedup 1.0000x reference)
#include <cuda_runtime.h>
#include <math.h>

#define BQ 2
#define LQ 2048
#define KQ 32
#define NRES (BQ*LQ)

// Scratch (allocation-free rule: __device__ globals)
__device__ __align__(16) float g_coords5[NRES * 15];   // 5 atoms x 3 per residue
__device__ __align__(16) float g_petab[65 * 64];       // pe(rel) @ W_pe + b_edge

// ---------------------------------------------------------------------------
// K1: per-residue virtual-CB + packed 5-atom coords
// ---------------------------------------------------------------------------
__global__ void k_coords(const float* __restrict__ coords) {
    int r = blockIdx.x * blockDim.x + threadIdx.x;
    if (r >= NRES) return;
    const float* c = coords + (size_t)r * 12;
    float n0 = c[0], n1 = c[1], n2 = c[2];
    float a0 = c[3], a1 = c[4], a2 = c[5];
    float c0 = c[6], c1 = c[7], c2 = c[8];

    // ca_n = normalize(n - ca)
    float ux = n0 - a0, uy = n1 - a1, uz = n2 - a2;
    float un = fmaxf(__fsqrt_rn(ux*ux + uy*uy + uz*uz), 1e-12f);
    ux = __fdiv_rn(ux, un); uy = __fdiv_rn(uy, un); uz = __fdiv_rn(uz, un);
    // ca_c = normalize(c - ca)
    float vx = c0 - a0, vy = c1 - a1, vz = c2 - a2;
    float vn = fmaxf(__fsqrt_rn(vx*vx + vy*vy + vz*vz), 1e-12f);
    vx = __fdiv_rn(vx, vn); vy = __fdiv_rn(vy, vn); vz = __fdiv_rn(vz, vn);
    // bisector = normalize(u + v)
    float bx = ux + vx, by = uy + vy, bz = uz + vz;
    float bn = fmaxf(__fsqrt_rn(bx*bx + by*by + bz*bz), 1e-12f);
    bx = __fdiv_rn(bx, bn); by = __fdiv_rn(by, bn); bz = __fdiv_rn(bz, bn);
    // perpendicular = normalize(cross(u, v))
    float px = uy*vz - uz*vy;
    float py = uz*vx - ux*vz;
    float pz = ux*vy - uy*vx;
    float pn = fmaxf(__fsqrt_rn(px*px + py*py + pz*pz), 1e-12f);
    px = __fdiv_rn(px, pn); py = __fdiv_rn(py, pn); pz = __fdiv_rn(pz, pn);
    // cb_dir = normalize(-bisector + 0.5*perpendicular)
    float dx = -bx + 0.5f*px, dy = -by + 0.5f*py, dz = -bz + 0.5f*pz;
    float dn = fmaxf(__fsqrt_rn(dx*dx + dy*dy + dz*dz), 1e-12f);
    dx = __fdiv_rn(dx, dn); dy = __fdiv_rn(dy, dn); dz = __fdiv_rn(dz, dn);

    float* o = g_coords5 + (size_t)r * 15;
    #pragma unroll
    for (int i = 0; i < 12; i++) o[i] = c[i];
    o[12] = a0 + 1.54f * dx;
    o[13] = a1 + 1.54f * dy;
    o[14] = a2 + 1.54f * dz;
}

// ---------------------------------------------------------------------------
// K2: PE table — g_petab[rel+32][h] = sum_p pe_p(rel) * W_pe[p][h] + b_edge[h]
// rel in [-32,32]; pe interleaves sin/cos of rel*div_term[j]
// ---------------------------------------------------------------------------
__global__ void k_petab(const float* __restrict__ W, const float* __restrict__ bvec) {
    int h = threadIdx.x;                  // 0..63
    int rb = blockIdx.x;                  // 0..64
    float rel = (float)(rb - 32);
    const float coef = (float)(-0.14391156831212787); // -ln(10000)/64
    float acc = bvec[h];
    #pragma unroll
    for (int j = 0; j < 32; j++) {
        float dt = expf((float)(2 * j) * coef);
        float ang = rel * dt;
        acc += sinf(ang) * W[(925 + 2*j)     * 64 + h];
        acc += cosf(ang) * W[(925 + 2*j + 1) * 64 + h];
    }
    g_petab[rb * 64 + h] = acc;
}

// ---------------------------------------------------------------------------
// K3: main — one CTA per (b,l); 256 threads
//   phase 1: load nb indices + rel + self coords
//   phase 2: stage 32 neighbors' 5-atom coords in smem
//   phase 3: 800 distances -> bin row ids (uint16) in smem
//   phase 4: 512 float4 chunks: acc = PE_table + sum of 25 gathered W rows
// ---------------------------------------------------------------------------
__global__ void __launch_bounds__(256)
k_main(const int* __restrict__ nidx, const float* __restrict__ W,
       float* __restrict__ out) {
    __shared__ float s_self[15];
    __shared__ float s_nb[32 * 16];       // padded stride 16
    __shared__ int   s_nbidx[32];
    __shared__ int   s_rel[32];
    __shared__ unsigned short s_row[800];

    const int tid = threadIdx.x;
    const int bid = blockIdx.x;           // = b*L + l
    const int b   = bid >> 11;
    const int l   = bid & (LQ - 1);

    if (tid < 32) {
        int nb = nidx[bid * KQ + tid];
        s_nbidx[tid] = nb;
        int rel = nb - l;
        rel = max(-32, min(32, rel));
        s_rel[tid] = rel + 32;
    } else if (tid < 47) {
        s_self[tid - 32] = g_coords5[bid * 15 + (tid - 32)];
    }
    __syncthreads();

    const int base = b * LQ;
    for (int j = tid; j < 480; j += 256) {
        int k = j / 15;
        int c = j - k * 15;
        s_nb[k * 16 + c] = g_coords5[(base + s_nbidx[k]) * 15 + c];
    }
    __syncthreads();

    for (int j = tid; j < 800; j += 256) {
        int k = j / 25;
        int p = j - k * 25;
        int a = p / 5;
        int q = p - a * 5;
        float dx = s_self[a*3 + 0] - s_nb[k*16 + q*3 + 0];
        float dy = s_self[a*3 + 1] - s_nb[k*16 + q*3 + 1];
        float dz = s_self[a*3 + 2] - s_nb[k*16 + q*3 + 2];
        float d = __fsqrt_rn(dx*dx + dy*dy + dz*dz);
        // searchsorted-left on bins 2.0+0.5*i, exact at representable boundaries
        int i = (int)ceilf((d - 2.0f) * 2.0f);
        i = max(0, min(36, i));
        s_row[j] = (unsigned short)(p * 37 + i);
    }
    __syncthreads();

    const float4* __restrict__ W4 = (const float4*)W;
    const float4* __restrict__ P4 = (const float4*)g_petab;
    float4* out4 = (float4*)out + (size_t)bid * 512;

    #pragma unroll
    for (int cc = 0; cc < 2; cc++) {
        int c    = tid + cc * 256;        // 0..511
        int k    = c >> 4;                // tuple 0..31
        int lane = c & 15;                // float4 chunk 0..15
        float4 acc = P4[s_rel[k] * 16 + lane];
        const unsigned short* rows = &s_row[k * 25];
        #pragma unroll
        for (int p = 0; p < 25; p++) {
            float4 w = W4[(int)rows[p] * 16 + lane];
            acc.x += w.x; acc.y += w.y; acc.z += w.z; acc.w += w.w;
        }
        out4[c] = acc;
    }
}

// ---------------------------------------------------------------------------
extern "C" void kernel_launch(void* const* d_in, const int* in_sizes, int n_in,
                              void* d_out, int out_size) {
    const float* coords = (const float*)d_in[0];   // (2,2048,4,3) f32
    const int*   nidx   = (const int*)  d_in[1];   // (2,2048,32) i32
    const float* W      = (const float*)d_in[2];   // (989,64) f32
    const float* bvec   = (const float*)d_in[3];   // (64,) f32

    k_coords<<<(NRES + 127) / 128, 128>>>(coords);
    k_petab<<<65, 64>>>(W, bvec);
    k_main<<<NRES, 256>>>(nidx, W, (float*)d_out);
}

// round 2
// speedup vs baseline: 1.1919x; 1.1919x over previous
#include <cuda_runtime.h>
#include <cuda_fp16.h>
#include <math.h>

#define BQ 2
#define LQ 2048
#define KQ 32
#define NRES (BQ*LQ)

// Scratch (allocation-free rule: __device__ globals)
__device__ __align__(16) float  g_petab[65 * 64];    // pe(rel) @ W_pe + b_edge (fp32)
__device__ __align__(16) __half g_wh[925 * 64];      // W_dist in fp16

// ---------------------------------------------------------------------------
// Prologue: blocks 0..64 build the PE table; blocks 65.. convert W_dist to fp16
// ---------------------------------------------------------------------------
__global__ void k_prep(const float* __restrict__ W, const float* __restrict__ bvec) {
    int blk = blockIdx.x, tid = threadIdx.x;
    if (blk < 65) {
        if (tid < 64) {
            float rel = (float)(blk - 32);
            const float coef = -0.14391156831212787f;   // -ln(10000)/64
            float acc = bvec[tid];
            #pragma unroll
            for (int j = 0; j < 32; j++) {
                float dt  = expf((float)(2 * j) * coef);
                float ang = rel * dt;
                acc += sinf(ang) * W[(925 + 2*j)     * 64 + tid];
                acc += cosf(ang) * W[(925 + 2*j + 1) * 64 + tid];
            }
            g_petab[blk * 64 + tid] = acc;
        }
    } else {
        int i = (blk - 65) * 256 + tid;
        if (i < 925 * 64) g_wh[i] = __float2half_rn(W[i]);
    }
}

// ---------------------------------------------------------------------------
// Main: one CTA per (b,l); 256 threads
//  phase 0: threads 0..32 compute 5-atom coords (incl. virtual CB) for the
//           32 neighbors + self, directly into smem
//  phase 1: 800 distances -> bin row ids (uint16) in smem
//  phase 2: 8 lanes per tuple; each lane accumulates 8 h-values in fp32 from
//           25 gathered fp16 rows (one uint4 = full 128B row per tuple)
// ---------------------------------------------------------------------------
__global__ void __launch_bounds__(256)
k_main(const float* __restrict__ coords, const int* __restrict__ nidx,
       float* __restrict__ out) {
    __shared__ float s_c5[33 * 16];       // 5 atoms x 3 (padded stride 16); [32] = self
    __shared__ int   s_rel[32];
    __shared__ unsigned short s_row[800];

    const int tid = threadIdx.x;
    const int bid = blockIdx.x;           // = b*L + l
    const int b   = bid >> 11;
    const int l   = bid & (LQ - 1);
    const int base = b * LQ;

    if (tid < 33) {
        int r;
        if (tid < 32) {
            int nb = nidx[bid * KQ + tid];
            int rel = max(-32, min(32, nb - l));
            s_rel[tid] = rel + 32;
            r = base + nb;
        } else {
            r = bid;
        }
        const float* c = coords + (size_t)r * 12;
        float n0 = c[0], n1 = c[1],  n2 = c[2];
        float a0 = c[3], a1 = c[4],  a2 = c[5];
        float c0 = c[6], c1 = c[7],  c2 = c[8];
        float o0 = c[9], o1 = c[10], o2 = c[11];

        // ca_n = normalize(n - ca)
        float ux = n0 - a0, uy = n1 - a1, uz = n2 - a2;
        float un = fmaxf(__fsqrt_rn(ux*ux + uy*uy + uz*uz), 1e-12f);
        ux = __fdiv_rn(ux, un); uy = __fdiv_rn(uy, un); uz = __fdiv_rn(uz, un);
        // ca_c = normalize(c - ca)
        float vx = c0 - a0, vy = c1 - a1, vz = c2 - a2;
        float vn = fmaxf(__fsqrt_rn(vx*vx + vy*vy + vz*vz), 1e-12f);
        vx = __fdiv_rn(vx, vn); vy = __fdiv_rn(vy, vn); vz = __fdiv_rn(vz, vn);
        // bisector = normalize(u + v)
        float bx = ux + vx, by = uy + vy, bz = uz + vz;
        float bn = fmaxf(__fsqrt_rn(bx*bx + by*by + bz*bz), 1e-12f);
        bx = __fdiv_rn(bx, bn); by = __fdiv_rn(by, bn); bz = __fdiv_rn(bz, bn);
        // perpendicular = normalize(cross(u, v))
        float px = uy*vz - uz*vy;
        float py = uz*vx - ux*vz;
        float pz = ux*vy - uy*vx;
        float pn = fmaxf(__fsqrt_rn(px*px + py*py + pz*pz), 1e-12f);
        px = __fdiv_rn(px, pn); py = __fdiv_rn(py, pn); pz = __fdiv_rn(pz, pn);
        // cb_dir = normalize(-bisector + 0.5*perpendicular)
        float dx = -bx + 0.5f*px, dy = -by + 0.5f*py, dz = -bz + 0.5f*pz;
        float dn = fmaxf(__fsqrt_rn(dx*dx + dy*dy + dz*dz), 1e-12f);
        dx = __fdiv_rn(dx, dn); dy = __fdiv_rn(dy, dn); dz = __fdiv_rn(dz, dn);

        float* o = &s_c5[tid * 16];
        o[0] = n0; o[1]  = n1; o[2]  = n2;
        o[3] = a0; o[4]  = a1; o[5]  = a2;
        o[6] = c0; o[7]  = c1; o[8]  = c2;
        o[9] = o0; o[10] = o1; o[11] = o2;
        o[12] = a0 + 1.54f * dx;
        o[13] = a1 + 1.54f * dy;
        o[14] = a2 + 1.54f * dz;
    }
    __syncthreads();

    for (int j = tid; j < 800; j += 256) {
        int k = j / 25;
        int p = j - k * 25;
        int a = p / 5;                    // self atom
        int q = p - a * 5;                // neighbor atom
        float dx = s_c5[32*16 + a*3 + 0] - s_c5[k*16 + q*3 + 0];
        float dy = s_c5[32*16 + a*3 + 1] - s_c5[k*16 + q*3 + 1];
        float dz = s_c5[32*16 + a*3 + 2] - s_c5[k*16 + q*3 + 2];
        float d = __fsqrt_rn(dx*dx + dy*dy + dz*dz);
        // searchsorted-left on bins 2.0 + 0.5*i, exact at representable boundaries
        int i = (int)ceilf((d - 2.0f) * 2.0f);
        i = max(0, min(36, i));
        s_row[j] = (unsigned short)(p * 37 + i);
    }
    __syncthreads();

    const int k    = tid >> 3;            // tuple 0..31
    const int lane = tid & 7;             // 8 h-values each

    const float4* __restrict__ P4 = (const float4*)g_petab;
    float4 p0 = P4[s_rel[k] * 16 + 2*lane];
    float4 p1 = P4[s_rel[k] * 16 + 2*lane + 1];
    float ax = p0.x, ay = p0.y, az = p0.z, aw = p0.w;
    float bx = p1.x, by = p1.y, bz = p1.z, bw = p1.w;

    const uint4* __restrict__ Wv = (const uint4*)g_wh;   // 8 uint4 per 64-h row
    const unsigned short* rows = &s_row[k * 25];
    #pragma unroll
    for (int p = 0; p < 25; p++) {
        uint4 w = Wv[(int)rows[p] * 8 + lane];
        float2 f;
        f = __half22float2(*(const __half2*)&w.x); ax += f.x; ay += f.y;
        f = __half22float2(*(const __half2*)&w.y); az += f.x; aw += f.y;
        f = __half22float2(*(const __half2*)&w.z); bx += f.x; by += f.y;
        f = __half22float2(*(const __half2*)&w.w); bz += f.x; bw += f.y;
    }

    float4* out4 = (float4*)out + (size_t)bid * 512;
    out4[k * 16 + 2*lane]     = make_float4(ax, ay, az, aw);
    out4[k * 16 + 2*lane + 1] = make_float4(bx, by, bz, bw);
}

// ---------------------------------------------------------------------------
extern "C" void kernel_launch(void* const* d_in, const int* in_sizes, int n_in,
                              void* d_out, int out_size) {
    const float* coords = (const float*)d_in[0];   // (2,2048,4,3) f32
    const int*   nidx   = (const int*)  d_in[1];   // (2,2048,32) i32
    const float* W      = (const float*)d_in[2];   // (989,64) f32
    const float* bvec   = (const float*)d_in[3];   // (64,) f32

    k_prep<<<65 + (925*64 + 255)/256, 256>>>(W, bvec);
    k_main<<<NRES, 256>>>(coords, nidx, (float*)d_out);
}

// round 3
// speedup vs baseline: 1.2865x; 1.0794x over previous
#include <cuda_runtime.h>
#include <cuda_fp16.h>
#include <math.h>

#define BQ 2
#define LQ 2048
#define KQ 32
#define NRES (BQ*LQ)

// Scratch (allocation-free rule: __device__ globals)
__device__ __align__(16) float  g_petab[65 * 64];    // pe(rel) @ W_pe + b_edge (fp32)
__device__ __align__(16) __half g_wh[925 * 64];      // W_dist in fp16

// ---------------------------------------------------------------------------
// Prologue: blocks 0..64 build the PE table; blocks 65.. convert W_dist to fp16
// ---------------------------------------------------------------------------
__global__ void k_prep(const float* __restrict__ W, const float* __restrict__ bvec) {
    int blk = blockIdx.x, tid = threadIdx.x;
    if (blk < 65) {
        if (tid < 64) {
            float rel = (float)(blk - 32);
            const float coef = -0.14391156831212787f;   // -ln(10000)/64
            float acc = bvec[tid];
            #pragma unroll
            for (int j = 0; j < 32; j++) {
                float dt  = expf((float)(2 * j) * coef);
                float ang = rel * dt;
                acc += sinf(ang) * W[(925 + 2*j)     * 64 + tid];
                acc += cosf(ang) * W[(925 + 2*j + 1) * 64 + tid];
            }
            g_petab[blk * 64 + tid] = acc;
        }
    } else {
        int i = ((blk - 65) * 256 + tid) * 4;
        if (i < 925 * 64) {
            float4 v = *(const float4*)(W + i);
            __half2 h0 = __floats2half2_rn(v.x, v.y);
            __half2 h1 = __floats2half2_rn(v.z, v.w);
            uint2 u;
            u.x = *(unsigned*)&h0;
            u.y = *(unsigned*)&h1;
            *(uint2*)(g_wh + i) = u;
        }
    }
}

// ---------------------------------------------------------------------------
// Main: one CTA per (b,l); 256 threads
//  phase 0: threads 0..32 compute 5-atom coords (incl. virtual CB) into smem
//  phase 1: 800 distances -> bin row ids (u16, stride-32 per tuple) in smem
//  phase 2: 8 lanes/tuple; pairwise half2 row reduction, fp32 accumulate
// ---------------------------------------------------------------------------
__global__ void __launch_bounds__(256)
k_main(const float* __restrict__ coords, const int* __restrict__ nidx,
       float* __restrict__ out) {
    __shared__ float s_c5[33 * 16];       // 5 atoms x 3 (padded stride 16); [32] = self
    __shared__ int   s_rel[32];
    __shared__ __align__(16) unsigned short s_rowp[32 * 32];  // [tuple][pair], padded

    const int tid = threadIdx.x;
    const int bid = blockIdx.x;           // = b*L + l
    const int b   = bid >> 11;
    const int l   = bid & (LQ - 1);
    const int base = b * LQ;

    if (tid < 33) {
        int r;
        if (tid < 32) {
            int nb = nidx[bid * KQ + tid];
            int rel = max(-32, min(32, nb - l));
            s_rel[tid] = rel + 32;
            r = base + nb;
        } else {
            r = bid;
        }
        const float* c = coords + (size_t)r * 12;
        float n0 = c[0], n1 = c[1],  n2 = c[2];
        float a0 = c[3], a1 = c[4],  a2 = c[5];
        float c0 = c[6], c1 = c[7],  c2 = c[8];
        float o0 = c[9], o1 = c[10], o2 = c[11];

        // ca_n = normalize(n - ca)
        float ux = n0 - a0, uy = n1 - a1, uz = n2 - a2;
        float un = fmaxf(__fsqrt_rn(ux*ux + uy*uy + uz*uz), 1e-12f);
        ux = __fdiv_rn(ux, un); uy = __fdiv_rn(uy, un); uz = __fdiv_rn(uz, un);
        // ca_c = normalize(c - ca)
        float vx = c0 - a0, vy = c1 - a1, vz = c2 - a2;
        float vn = fmaxf(__fsqrt_rn(vx*vx + vy*vy + vz*vz), 1e-12f);
        vx = __fdiv_rn(vx, vn); vy = __fdiv_rn(vy, vn); vz = __fdiv_rn(vz, vn);
        // bisector = normalize(u + v)
        float bx = ux + vx, by = uy + vy, bz = uz + vz;
        float bn = fmaxf(__fsqrt_rn(bx*bx + by*by + bz*bz), 1e-12f);
        bx = __fdiv_rn(bx, bn); by = __fdiv_rn(by, bn); bz = __fdiv_rn(bz, bn);
        // perpendicular = normalize(cross(u, v))
        float px = uy*vz - uz*vy;
        float py = uz*vx - ux*vz;
        float pz = ux*vy - uy*vx;
        float pn = fmaxf(__fsqrt_rn(px*px + py*py + pz*pz), 1e-12f);
        px = __fdiv_rn(px, pn); py = __fdiv_rn(py, pn); pz = __fdiv_rn(pz, pn);
        // cb_dir = normalize(-bisector + 0.5*perpendicular)
        float dx = -bx + 0.5f*px, dy = -by + 0.5f*py, dz = -bz + 0.5f*pz;
        float dn = fmaxf(__fsqrt_rn(dx*dx + dy*dy + dz*dz), 1e-12f);
        dx = __fdiv_rn(dx, dn); dy = __fdiv_rn(dy, dn); dz = __fdiv_rn(dz, dn);

        float* o = &s_c5[tid * 16];
        o[0] = n0; o[1]  = n1; o[2]  = n2;
        o[3] = a0; o[4]  = a1; o[5]  = a2;
        o[6] = c0; o[7]  = c1; o[8]  = c2;
        o[9] = o0; o[10] = o1; o[11] = o2;
        o[12] = a0 + 1.54f * dx;
        o[13] = a1 + 1.54f * dy;
        o[14] = a2 + 1.54f * dz;
    }
    __syncthreads();

    for (int j = tid; j < 800; j += 256) {
        int k = j / 25;
        int p = j - k * 25;
        int a = p / 5;                    // self atom
        int q = p - a * 5;                // neighbor atom
        float dx = s_c5[32*16 + a*3 + 0] - s_c5[k*16 + q*3 + 0];
        float dy = s_c5[32*16 + a*3 + 1] - s_c5[k*16 + q*3 + 1];
        float dz = s_c5[32*16 + a*3 + 2] - s_c5[k*16 + q*3 + 2];
        float d = __fsqrt_rn(dx*dx + dy*dy + dz*dz);
        // searchsorted-left on bins 2.0 + 0.5*i, exact at representable boundaries
        int i = (int)ceilf((d - 2.0f) * 2.0f);
        i = max(0, min(36, i));
        s_rowp[k * 32 + p] = (unsigned short)(p * 37 + i);
    }
    __syncthreads();

    const int k    = tid >> 3;            // tuple 0..31
    const int lane = tid & 7;             // 8 h-values each

    // fp32 accumulators, seeded from the PE table
    const float4* __restrict__ P4 = (const float4*)g_petab;
    float4 A0 = P4[s_rel[k] * 16 + 2*lane];
    float4 A1 = P4[s_rel[k] * 16 + 2*lane + 1];

    // packed row ids: 13 u32 words (25 u16 rows + 1 pad)
    const unsigned* wp = (const unsigned*)&s_rowp[k * 32];
    unsigned wpk[13];
    #pragma unroll
    for (int i = 0; i < 12; i += 4) {
        uint4 t = *(const uint4*)&wp[i];
        wpk[i] = t.x; wpk[i+1] = t.y; wpk[i+2] = t.z; wpk[i+3] = t.w;
    }
    wpk[12] = wp[12];

    const uint4* __restrict__ Wv = (const uint4*)g_wh;   // 8 uint4 per 64-h row

    #pragma unroll
    for (int g = 0; g < 12; g++) {
        unsigned w2 = wpk[g];
        uint4 ra = Wv[(w2 & 0xffffu) * 8 + lane];
        uint4 rb = Wv[(w2 >> 16)     * 8 + lane];
        __half2 s0 = __hadd2(*(__half2*)&ra.x, *(__half2*)&rb.x);
        __half2 s1 = __hadd2(*(__half2*)&ra.y, *(__half2*)&rb.y);
        __half2 s2 = __hadd2(*(__half2*)&ra.z, *(__half2*)&rb.z);
        __half2 s3 = __hadd2(*(__half2*)&ra.w, *(__half2*)&rb.w);
        float2 f;
        f = __half22float2(s0); A0.x += f.x; A0.y += f.y;
        f = __half22float2(s1); A0.z += f.x; A0.w += f.y;
        f = __half22float2(s2); A1.x += f.x; A1.y += f.y;
        f = __half22float2(s3); A1.z += f.x; A1.w += f.y;
    }
    {   // leftover 25th row, direct fp32 accumulate
        uint4 ra = Wv[(wpk[12] & 0xffffu) * 8 + lane];
        float2 f;
        f = __half22float2(*(__half2*)&ra.x); A0.x += f.x; A0.y += f.y;
        f = __half22float2(*(__half2*)&ra.y); A0.z += f.x; A0.w += f.y;
        f = __half22float2(*(__half2*)&ra.z); A1.x += f.x; A1.y += f.y;
        f = __half22float2(*(__half2*)&ra.w); A1.z += f.x; A1.w += f.y;
    }

    float4* out4 = (float4*)out + (size_t)bid * 512;
    out4[k * 16 + 2*lane]     = A0;
    out4[k * 16 + 2*lane + 1] = A1;
}

// ---------------------------------------------------------------------------
extern "C" void kernel_launch(void* const* d_in, const int* in_sizes, int n_in,
                              void* d_out, int out_size) {
    const float* coords = (const float*)d_in[0];   // (2,2048,4,3) f32
    const int*   nidx   = (const int*)  d_in[1];   // (2,2048,32) i32
    const float* W      = (const float*)d_in[2];   // (989,64) f32
    const float* bvec   = (const float*)d_in[3];   // (64,) f32

    k_prep<<<65 + (925*64/4 + 255)/256, 256>>>(W, bvec);
    k_main<<<NRES, 256>>>(coords, nidx, (float*)d_out);
}

// round 4
// speedup vs baseline: 1.3411x; 1.0425x over previous
#include <cuda_runtime.h>
#include <cuda_fp16.h>
#include <math.h>

#define BQ 2
#define LQ 2048
#define KQ 32
#define NRES (BQ*LQ)

// Scratch (allocation-free rule: __device__ globals)
__device__ __align__(16) float  g_petab[65 * 64];     // pe(rel) @ W_pe + b_edge (fp32)
__device__ __align__(16) __half g_wh[925 * 64];       // W_dist in fp16
__device__ __align__(16) float  g_c5[NRES * 16];      // 5 atoms x 3, padded to 16

__device__ __forceinline__ float sqrt_approx(float s) {
    float d;
    asm("sqrt.approx.f32 %0, %1;" : "=f"(d) : "f"(s));
    return d;
}

// ---------------------------------------------------------------------------
// Prologue (one kernel, independent block ranges):
//   blocks [0,65)        : PE table (65 rel values x 64 h)
//   blocks [65,81)       : per-residue 5-atom coords incl. virtual CB
//   blocks [81,...)      : W_dist fp32 -> fp16 conversion
// ---------------------------------------------------------------------------
__global__ void k_prep(const float* __restrict__ W, const float* __restrict__ bvec,
                       const float* __restrict__ coords) {
    int blk = blockIdx.x, tid = threadIdx.x;
    if (blk < 65) {
        if (tid < 64) {
            float rel = (float)(blk - 32);
            const float coef = -0.14391156831212787f;   // -ln(10000)/64
            float acc = bvec[tid];
            #pragma unroll
            for (int j = 0; j < 32; j++) {
                float dt  = expf((float)(2 * j) * coef);
                float ang = rel * dt;
                acc += sinf(ang) * W[(925 + 2*j)     * 64 + tid];
                acc += cosf(ang) * W[(925 + 2*j + 1) * 64 + tid];
            }
            g_petab[blk * 64 + tid] = acc;
        }
    } else if (blk < 81) {
        int r = (blk - 65) * 256 + tid;    // 0..4095
        const float* c = coords + (size_t)r * 12;
        float n0 = c[0], n1 = c[1],  n2 = c[2];
        float a0 = c[3], a1 = c[4],  a2 = c[5];
        float c0 = c[6], c1 = c[7],  c2 = c[8];
        float o0 = c[9], o1 = c[10], o2 = c[11];

        // ca_n = normalize(n - ca)
        float ux = n0 - a0, uy = n1 - a1, uz = n2 - a2;
        float un = fmaxf(__fsqrt_rn(ux*ux + uy*uy + uz*uz), 1e-12f);
        ux = __fdiv_rn(ux, un); uy = __fdiv_rn(uy, un); uz = __fdiv_rn(uz, un);
        // ca_c = normalize(c - ca)
        float vx = c0 - a0, vy = c1 - a1, vz = c2 - a2;
        float vn = fmaxf(__fsqrt_rn(vx*vx + vy*vy + vz*vz), 1e-12f);
        vx = __fdiv_rn(vx, vn); vy = __fdiv_rn(vy, vn); vz = __fdiv_rn(vz, vn);
        // bisector = normalize(u + v)
        float bx = ux + vx, by = uy + vy, bz = uz + vz;
        float bn = fmaxf(__fsqrt_rn(bx*bx + by*by + bz*bz), 1e-12f);
        bx = __fdiv_rn(bx, bn); by = __fdiv_rn(by, bn); bz = __fdiv_rn(bz, bn);
        // perpendicular = normalize(cross(u, v))
        float px = uy*vz - uz*vy;
        float py = uz*vx - ux*vz;
        float pz = ux*vy - uy*vx;
        float pn = fmaxf(__fsqrt_rn(px*px + py*py + pz*pz), 1e-12f);
        px = __fdiv_rn(px, pn); py = __fdiv_rn(py, pn); pz = __fdiv_rn(pz, pn);
        // cb_dir = normalize(-bisector + 0.5*perpendicular)
        float dx = -bx + 0.5f*px, dy = -by + 0.5f*py, dz = -bz + 0.5f*pz;
        float dn = fmaxf(__fsqrt_rn(dx*dx + dy*dy + dz*dz), 1e-12f);
        dx = __fdiv_rn(dx, dn); dy = __fdiv_rn(dy, dn); dz = __fdiv_rn(dz, dn);

        float* o = g_c5 + (size_t)r * 16;
        float4* o4 = (float4*)o;
        o4[0] = make_float4(n0, n1, n2, a0);
        o4[1] = make_float4(a1, a2, c0, c1);
        o4[2] = make_float4(c2, o0, o1, o2);
        o4[3] = make_float4(a0 + 1.54f*dx, a1 + 1.54f*dy, a2 + 1.54f*dz, 0.f);
    } else {
        int i = ((blk - 81) * 256 + tid) * 4;
        if (i < 925 * 64) {
            float4 v = *(const float4*)(W + i);
            __half2 h0 = __floats2half2_rn(v.x, v.y);
            __half2 h1 = __floats2half2_rn(v.z, v.w);
            uint2 u;
            u.x = *(unsigned*)&h0;
            u.y = *(unsigned*)&h1;
            *(uint2*)(g_wh + i) = u;
        }
    }
}

// s_c5 layout per residue slot (stride 16 floats), from k_prep packing:
//  [0..2]=N  [3..5]=CA  [6..8]=C  [9..11]=O  [12..14]=CB
// Atom a coord c at index a*3+c.

// ---------------------------------------------------------------------------
// Main: one CTA per (b,l); 256 threads
// ---------------------------------------------------------------------------
__global__ void __launch_bounds__(256)
k_main(const int* __restrict__ nidx, float* __restrict__ out) {
    __shared__ float s_c5[33 * 16];       // 32 neighbors + self(32)
    __shared__ int   s_rel[32];
    __shared__ int   s_nbr[32];
    __shared__ __align__(16) unsigned short s_rowp[32 * 32];  // [tuple][pair]

    const int tid = threadIdx.x;
    const int bid = blockIdx.x;           // = b*L + l
    const int b   = bid >> 11;
    const int l   = bid & (LQ - 1);
    const int base = b * LQ;

    if (tid < 32) {
        int nb = nidx[bid * KQ + tid];
        s_nbr[tid] = base + nb;
        int rel = max(-32, min(32, nb - l));
        s_rel[tid] = rel + 32;
    }
    __syncthreads();

    if (tid < 132) {
        int resid = tid >> 2;             // 0..32
        int word  = tid & 3;
        int r = (resid < 32) ? s_nbr[resid] : bid;
        ((float4*)s_c5)[resid * 4 + word] = ((const float4*)g_c5)[r * 4 + word];
    }
    __syncthreads();

    for (int j = tid; j < 800; j += 256) {
        int k = j / 25;
        int p = j - k * 25;
        int a = p / 5;                    // self atom
        int q = p - a * 5;                // neighbor atom
        float dx = s_c5[32*16 + a*3 + 0] - s_c5[k*16 + q*3 + 0];
        float dy = s_c5[32*16 + a*3 + 1] - s_c5[k*16 + q*3 + 1];
        float dz = s_c5[32*16 + a*3 + 2] - s_c5[k*16 + q*3 + 2];
        float d = sqrt_approx(dx*dx + dy*dy + dz*dz);
        // searchsorted-left on bins 2.0 + 0.5*i
        int i = (int)ceilf((d - 2.0f) * 2.0f);
        i = max(0, min(36, i));
        s_rowp[k * 32 + p] = (unsigned short)(p * 37 + i);
    }
    __syncthreads();

    const int k    = tid >> 3;            // tuple 0..31
    const int lane = tid & 7;             // 8 h-values each

    const float4* __restrict__ P4 = (const float4*)g_petab;
    float4 A0 = P4[s_rel[k] * 16 + 2*lane];
    float4 A1 = P4[s_rel[k] * 16 + 2*lane + 1];

    const unsigned* wp = (const unsigned*)&s_rowp[k * 32];
    const uint4* __restrict__ Wv = (const uint4*)g_wh;   // 8 uint4 per 64-h row

    #pragma unroll
    for (int g = 0; g < 6; g++) {
        uint2 w = *(const uint2*)&wp[2*g];          // 4 row ids
        uint4 r0 = Wv[(w.x & 0xffffu) * 8 + lane];
        uint4 r1 = Wv[(w.x >> 16)     * 8 + lane];
        uint4 r2 = Wv[(w.y & 0xffffu) * 8 + lane];
        uint4 r3 = Wv[(w.y >> 16)     * 8 + lane];
        __half2 s0 = __hadd2(__hadd2(*(__half2*)&r0.x, *(__half2*)&r1.x),
                             __hadd2(*(__half2*)&r2.x, *(__half2*)&r3.x));
        __half2 s1 = __hadd2(__hadd2(*(__half2*)&r0.y, *(__half2*)&r1.y),
                             __hadd2(*(__half2*)&r2.y, *(__half2*)&r3.y));
        __half2 s2 = __hadd2(__hadd2(*(__half2*)&r0.z, *(__half2*)&r1.z),
                             __hadd2(*(__half2*)&r2.z, *(__half2*)&r3.z));
        __half2 s3 = __hadd2(__hadd2(*(__half2*)&r0.w, *(__half2*)&r1.w),
                             __hadd2(*(__half2*)&r2.w, *(__half2*)&r3.w));
        float2 f;
        f = __half22float2(s0); A0.x += f.x; A0.y += f.y;
        f = __half22float2(s1); A0.z += f.x; A0.w += f.y;
        f = __half22float2(s2); A1.x += f.x; A1.y += f.y;
        f = __half22float2(s3); A1.z += f.x; A1.w += f.y;
    }
    {   // leftover 25th row
        uint4 ra = Wv[(wp[12] & 0xffffu) * 8 + lane];
        float2 f;
        f = __half22float2(*(__half2*)&ra.x); A0.x += f.x; A0.y += f.y;
        f = __half22float2(*(__half2*)&ra.y); A0.z += f.x; A0.w += f.y;
        f = __half22float2(*(__half2*)&ra.z); A1.x += f.x; A1.y += f.y;
        f = __half22float2(*(__half2*)&ra.w); A1.z += f.x; A1.w += f.y;
    }

    float4* out4 = (float4*)out + (size_t)bid * 512;
    out4[k * 16 + 2*lane]     = A0;
    out4[k * 16 + 2*lane + 1] = A1;
}

// ---------------------------------------------------------------------------
extern "C" void kernel_launch(void* const* d_in, const int* in_sizes, int n_in,
                              void* d_out, int out_size) {
    const float* coords = (const float*)d_in[0];   // (2,2048,4,3) f32
    const int*   nidx   = (const int*)  d_in[1];   // (2,2048,32) i32
    const float* W      = (const float*)d_in[2];   // (989,64) f32
    const float* bvec   = (const float*)d_in[3];   // (64,) f32

    k_prep<<<81 + (925*64/4 + 255)/256, 256>>>(W, bvec, coords);
    k_main<<<NRES, 256>>>(nidx, (float*)d_out);
}

// round 6
// speedup vs baseline: 1.4136x; 1.0540x over previous
#include <cuda_runtime.h>
#include <cuda_fp16.h>
#include <math.h>

#define BQ 2
#define LQ 2048
#define KQ 32
#define NRES (BQ*LQ)

// Scratch (allocation-free rule: __device__ globals)
__device__ __align__(16) float  g_petab[65 * 64];     // pe(rel) @ W_pe + b_edge (fp32)
__device__ __align__(16) __half g_wh[925 * 64];       // W_dist in fp16
__device__ __align__(16) float  g_c5[NRES * 16];      // 5 atoms x 3, padded to 16

// packed pair decode: p*37 | (p/5*3)<<16 | (p%5*3)<<24
#define PAIR(p) ((p)*37 | ((p)/5*3)<<16 | ((p)%5*3)<<24)
__constant__ int c_pair[25] = {
    PAIR(0),  PAIR(1),  PAIR(2),  PAIR(3),  PAIR(4),
    PAIR(5),  PAIR(6),  PAIR(7),  PAIR(8),  PAIR(9),
    PAIR(10), PAIR(11), PAIR(12), PAIR(13), PAIR(14),
    PAIR(15), PAIR(16), PAIR(17), PAIR(18), PAIR(19),
    PAIR(20), PAIR(21), PAIR(22), PAIR(23), PAIR(24)
};

__device__ __forceinline__ float sqrt_approx(float s) {
    float d;
    asm("sqrt.approx.f32 %0, %1;" : "=f"(d) : "f"(s));
    return d;
}
__device__ __forceinline__ __half2 H2(unsigned u) { return *(__half2*)&u; }

// ---------------------------------------------------------------------------
// Prologue (one kernel, independent block ranges):
//   blocks [0,65)  : PE table;  [65,81) : coords5;  [81,..) : W fp16 convert
// ---------------------------------------------------------------------------
__global__ void k_prep(const float* __restrict__ W, const float* __restrict__ bvec,
                       const float* __restrict__ coords) {
    int blk = blockIdx.x, tid = threadIdx.x;
    if (blk < 65) {
        if (tid < 64) {
            float rel = (float)(blk - 32);
            const float coef = -0.14391156831212787f;   // -ln(10000)/64
            float acc = bvec[tid];
            #pragma unroll
            for (int j = 0; j < 32; j++) {
                float dt  = expf((float)(2 * j) * coef);
                float ang = rel * dt;
                acc += sinf(ang) * W[(925 + 2*j)     * 64 + tid];
                acc += cosf(ang) * W[(925 + 2*j + 1) * 64 + tid];
            }
            g_petab[blk * 64 + tid] = acc;
        }
    } else if (blk < 81) {
        int r = (blk - 65) * 256 + tid;    // 0..4095
        const float* c = coords + (size_t)r * 12;
        float n0 = c[0], n1 = c[1],  n2 = c[2];
        float a0 = c[3], a1 = c[4],  a2 = c[5];
        float c0 = c[6], c1 = c[7],  c2 = c[8];
        float o0 = c[9], o1 = c[10], o2 = c[11];

        float ux = n0 - a0, uy = n1 - a1, uz = n2 - a2;
        float un = fmaxf(__fsqrt_rn(ux*ux + uy*uy + uz*uz), 1e-12f);
        ux = __fdiv_rn(ux, un); uy = __fdiv_rn(uy, un); uz = __fdiv_rn(uz, un);
        float vx = c0 - a0, vy = c1 - a1, vz = c2 - a2;
        float vn = fmaxf(__fsqrt_rn(vx*vx + vy*vy + vz*vz), 1e-12f);
        vx = __fdiv_rn(vx, vn); vy = __fdiv_rn(vy, vn); vz = __fdiv_rn(vz, vn);
        float bx = ux + vx, by = uy + vy, bz = uz + vz;
        float bn = fmaxf(__fsqrt_rn(bx*bx + by*by + bz*bz), 1e-12f);
        bx = __fdiv_rn(bx, bn); by = __fdiv_rn(by, bn); bz = __fdiv_rn(bz, bn);
        float px = uy*vz - uz*vy;
        float py = uz*vx - ux*vz;
        float pz = ux*vy - uy*vx;
        float pn = fmaxf(__fsqrt_rn(px*px + py*py + pz*pz), 1e-12f);
        px = __fdiv_rn(px, pn); py = __fdiv_rn(py, pn); pz = __fdiv_rn(pz, pn);
        float dx = -bx + 0.5f*px, dy = -by + 0.5f*py, dz = -bz + 0.5f*pz;
        float dn = fmaxf(__fsqrt_rn(dx*dx + dy*dy + dz*dz), 1e-12f);
        dx = __fdiv_rn(dx, dn); dy = __fdiv_rn(dy, dn); dz = __fdiv_rn(dz, dn);

        float4* o4 = (float4*)(g_c5 + (size_t)r * 16);
        o4[0] = make_float4(n0, n1, n2, a0);
        o4[1] = make_float4(a1, a2, c0, c1);
        o4[2] = make_float4(c2, o0, o1, o2);
        o4[3] = make_float4(a0 + 1.54f*dx, a1 + 1.54f*dy, a2 + 1.54f*dz, 0.f);
    } else {
        int i = ((blk - 81) * 256 + tid) * 4;
        if (i < 925 * 64) {
            float4 v = *(const float4*)(W + i);
            __half2 h0 = __floats2half2_rn(v.x, v.y);
            __half2 h1 = __floats2half2_rn(v.z, v.w);
            uint2 u;
            u.x = *(unsigned*)&h0;
            u.y = *(unsigned*)&h1;
            *(uint2*)(g_wh + i) = u;
        }
    }
}

// ---------------------------------------------------------------------------
// Main: one CTA per (b,l); 256 threads = 8 autonomous warps, 4 tuples each.
// No __syncthreads — only __syncwarp. All shuffles warp-uniform (no divergent
// __shfl_sync — that was the round-5 illegal-access bug).
//   coords5 layout per residue slot: [0..2]=N [3..5]=CA [6..8]=C [9..11]=O [12..14]=CB
// ---------------------------------------------------------------------------
__global__ void __launch_bounds__(256)
k_main(const int* __restrict__ nidx, float* __restrict__ out) {
    __shared__ float s_c5[8][5 * 16];                  // per-warp: 4 nb + self(4)
    __shared__ __align__(16) unsigned short s_rows[8][4][32];  // 25 used per tuple

    const int tid  = threadIdx.x;
    const int lane = tid & 31;
    const int w    = tid >> 5;
    const int bid  = blockIdx.x;          // = b*L + l
    const int b    = bid >> 11;
    const int l    = bid & (LQ - 1);
    const int base = b * LQ;

    // Phase A: indices + coords (warp-local). Shuffles executed by ALL lanes.
    int r4 = bid, relreg = 0;
    if (lane < 4) {
        int nb = nidx[bid * KQ + w * 4 + lane];
        relreg = max(-32, min(32, nb - l)) + 32;
        r4 = base + nb;
    }
    {
        int resid = (lane >> 2) & 7;      // 0..4 for lanes<20; 5..7 for rest (unused)
        int word  = lane & 3;
        int rsel  = __shfl_sync(0xFFFFFFFFu, r4, resid < 5 ? resid : 4);
        if (lane < 20)
            ((float4*)&s_c5[w][0])[resid * 4 + word] = ((const float4*)g_c5)[rsel * 4 + word];
    }
    __syncwarp();

    // Phase B: 100 distances -> bin rows (u16) in warp smem
    int e = c_pair[lane < 25 ? lane : 0];
    int rbase = e & 0xffff;               // p*37
    int a3 = (e >> 16) & 0xff;            // self atom offset
    int q3 = e >> 24;                     // neighbor atom offset
    float sx = s_c5[w][4*16 + a3 + 0];
    float sy = s_c5[w][4*16 + a3 + 1];
    float sz = s_c5[w][4*16 + a3 + 2];
    #pragma unroll
    for (int t = 0; t < 4; t++) {
        float dx = sx - s_c5[w][t*16 + q3 + 0];
        float dy = sy - s_c5[w][t*16 + q3 + 1];
        float dz = sz - s_c5[w][t*16 + q3 + 2];
        float d = sqrt_approx(dx*dx + dy*dy + dz*dz);
        int i = (int)ceilf((d - 2.0f) * 2.0f);   // searchsorted-left, bins 2.0+0.5i
        i = max(0, min(36, i));
        if (lane < 25)
            s_rows[w][t][lane] = (unsigned short)(rbase + i);
    }
    __syncwarp();

    // Phase C: gather-accumulate. 8 lanes per tuple, 8 h each.
    const int t  = lane >> 3;             // tuple within warp
    const int ln = lane & 7;
    const int rel_t = __shfl_sync(0xFFFFFFFFu, relreg, t);   // all lanes execute

    const float4* __restrict__ P4 = (const float4*)g_petab;
    float4 A0 = P4[rel_t * 16 + 2*ln];
    float4 A1 = P4[rel_t * 16 + 2*ln + 1];

    const unsigned* wp = (const unsigned*)&s_rows[w][t][0];
    const uint4* __restrict__ Wv = (const uint4*)g_wh;   // 8 uint4 per 64-h row

    #pragma unroll
    for (int g = 0; g < 3; g++) {         // 3 super-groups of 8 rows
        uint4 ww = *(const uint4*)&wp[4*g];
        uint4 r0 = Wv[(ww.x & 0xffffu) * 8 + ln];
        uint4 r1 = Wv[(ww.x >> 16)     * 8 + ln];
        uint4 r2 = Wv[(ww.y & 0xffffu) * 8 + ln];
        uint4 r3 = Wv[(ww.y >> 16)     * 8 + ln];
        __half2 s0 = __hadd2(__hadd2(H2(r0.x), H2(r1.x)), __hadd2(H2(r2.x), H2(r3.x)));
        __half2 s1 = __hadd2(__hadd2(H2(r0.y), H2(r1.y)), __hadd2(H2(r2.y), H2(r3.y)));
        __half2 s2 = __hadd2(__hadd2(H2(r0.z), H2(r1.z)), __hadd2(H2(r2.z), H2(r3.z)));
        __half2 s3 = __hadd2(__hadd2(H2(r0.w), H2(r1.w)), __hadd2(H2(r2.w), H2(r3.w)));
        uint4 r4a = Wv[(ww.z & 0xffffu) * 8 + ln];
        uint4 r5  = Wv[(ww.z >> 16)     * 8 + ln];
        uint4 r6  = Wv[(ww.w & 0xffffu) * 8 + ln];
        uint4 r7  = Wv[(ww.w >> 16)     * 8 + ln];
        s0 = __hadd2(s0, __hadd2(__hadd2(H2(r4a.x), H2(r5.x)), __hadd2(H2(r6.x), H2(r7.x))));
        s1 = __hadd2(s1, __hadd2(__hadd2(H2(r4a.y), H2(r5.y)), __hadd2(H2(r6.y), H2(r7.y))));
        s2 = __hadd2(s2, __hadd2(__hadd2(H2(r4a.z), H2(r5.z)), __hadd2(H2(r6.z), H2(r7.z))));
        s3 = __hadd2(s3, __hadd2(__hadd2(H2(r4a.w), H2(r5.w)), __hadd2(H2(r6.w), H2(r7.w))));
        float2 f;
        f = __half22float2(s0); A0.x += f.x; A0.y += f.y;
        f = __half22float2(s1); A0.z += f.x; A0.w += f.y;
        f = __half22float2(s2); A1.x += f.x; A1.y += f.y;
        f = __half22float2(s3); A1.z += f.x; A1.w += f.y;
    }
    {   // leftover 25th row (u16[24])
        uint4 ra = Wv[(wp[12] & 0xffffu) * 8 + ln];
        float2 f;
        f = __half22float2(H2(ra.x)); A0.x += f.x; A0.y += f.y;
        f = __half22float2(H2(ra.y)); A0.z += f.x; A0.w += f.y;
        f = __half22float2(H2(ra.z)); A1.x += f.x; A1.y += f.y;
        f = __half22float2(H2(ra.w)); A1.z += f.x; A1.w += f.y;
    }

    float4* out4 = (float4*)out + (size_t)bid * 512;
    const int kk = w * 4 + t;
    out4[kk * 16 + 2*ln]     = A0;
    out4[kk * 16 + 2*ln + 1] = A1;
}

// ---------------------------------------------------------------------------
extern "C" void kernel_launch(void* const* d_in, const int* in_sizes, int n_in,
                              void* d_out, int out_size) {
    const float* coords = (const float*)d_in[0];   // (2,2048,4,3) f32
    const int*   nidx   = (const int*)  d_in[1];   // (2,2048,32) i32
    const float* W      = (const float*)d_in[2];   // (989,64) f32
    const float* bvec   = (const float*)d_in[3];   // (64,) f32

    k_prep<<<81 + (925*64/4 + 255)/256, 256>>>(W, bvec, coords);
    k_main<<<NRES, 256>>>(nidx, (float*)d_out);
}

// round 7
// speedup vs baseline: 1.7498x; 1.2378x over previous
#include <cuda_runtime.h>
#include <cuda_fp16.h>
#include <math.h>

#define BQ 2
#define LQ 2048
#define KQ 32
#define NRES (BQ*LQ)

// Scratch (allocation-free rule: __device__ globals)
__device__ __align__(16) float  g_petab[65 * 64];     // pe(rel) @ W_pe + b_edge (fp32)
__device__ __align__(16) __half g_wh[925 * 64];       // W_dist in fp16
__device__ __align__(16) float  g_c5[NRES * 16];      // 5 atoms x 3, padded to 16

// packed pair decode: p*37 | (p/5*3)<<16 | (p%5*3)<<24
#define PAIR(p) ((p)*37 | ((p)/5*3)<<16 | ((p)%5*3)<<24)
__constant__ int c_pair[25] = {
    PAIR(0),  PAIR(1),  PAIR(2),  PAIR(3),  PAIR(4),
    PAIR(5),  PAIR(6),  PAIR(7),  PAIR(8),  PAIR(9),
    PAIR(10), PAIR(11), PAIR(12), PAIR(13), PAIR(14),
    PAIR(15), PAIR(16), PAIR(17), PAIR(18), PAIR(19),
    PAIR(20), PAIR(21), PAIR(22), PAIR(23), PAIR(24)
};

__device__ __forceinline__ float sqrt_approx(float s) {
    float d;
    asm("sqrt.approx.f32 %0, %1;" : "=f"(d) : "f"(s));
    return d;
}
__device__ __forceinline__ __half2 H2(unsigned u) { return *(__half2*)&u; }

// ---------------------------------------------------------------------------
// Prologue (one kernel, independent block ranges):
//   blocks [0,65)  : PE table;  [65,81) : coords5;  [81,..) : W fp16 convert
// ---------------------------------------------------------------------------
__global__ void k_prep(const float* __restrict__ W, const float* __restrict__ bvec,
                       const float* __restrict__ coords) {
    int blk = blockIdx.x, tid = threadIdx.x;
    if (blk < 65) {
        if (tid < 64) {
            float rel = (float)(blk - 32);
            const float coef = -0.14391156831212787f;   // -ln(10000)/64
            float acc = bvec[tid];
            #pragma unroll
            for (int j = 0; j < 32; j++) {
                float dt  = __expf((float)(2 * j) * coef);
                float ang = rel * dt;
                acc += __sinf(ang) * W[(925 + 2*j)     * 64 + tid];
                acc += __cosf(ang) * W[(925 + 2*j + 1) * 64 + tid];
            }
            g_petab[blk * 64 + tid] = acc;
        }
    } else if (blk < 81) {
        int r = (blk - 65) * 256 + tid;    // 0..4095
        const float* c = coords + (size_t)r * 12;
        float n0 = c[0], n1 = c[1],  n2 = c[2];
        float a0 = c[3], a1 = c[4],  a2 = c[5];
        float c0 = c[6], c1 = c[7],  c2 = c[8];
        float o0 = c[9], o1 = c[10], o2 = c[11];

        float ux = n0 - a0, uy = n1 - a1, uz = n2 - a2;
        float un = fmaxf(__fsqrt_rn(ux*ux + uy*uy + uz*uz), 1e-12f);
        ux = __fdiv_rn(ux, un); uy = __fdiv_rn(uy, un); uz = __fdiv_rn(uz, un);
        float vx = c0 - a0, vy = c1 - a1, vz = c2 - a2;
        float vn = fmaxf(__fsqrt_rn(vx*vx + vy*vy + vz*vz), 1e-12f);
        vx = __fdiv_rn(vx, vn); vy = __fdiv_rn(vy, vn); vz = __fdiv_rn(vz, vn);
        float bx = ux + vx, by = uy + vy, bz = uz + vz;
        float bn = fmaxf(__fsqrt_rn(bx*bx + by*by + bz*bz), 1e-12f);
        bx = __fdiv_rn(bx, bn); by = __fdiv_rn(by, bn); bz = __fdiv_rn(bz, bn);
        float px = uy*vz - uz*vy;
        float py = uz*vx - ux*vz;
        float pz = ux*vy - uy*vx;
        float pn = fmaxf(__fsqrt_rn(px*px + py*py + pz*pz), 1e-12f);
        px = __fdiv_rn(px, pn); py = __fdiv_rn(py, pn); pz = __fdiv_rn(pz, pn);
        float dx = -bx + 0.5f*px, dy = -by + 0.5f*py, dz = -bz + 0.5f*pz;
        float dn = fmaxf(__fsqrt_rn(dx*dx + dy*dy + dz*dz), 1e-12f);
        dx = __fdiv_rn(dx, dn); dy = __fdiv_rn(dy, dn); dz = __fdiv_rn(dz, dn);

        float4* o4 = (float4*)(g_c5 + (size_t)r * 16);
        o4[0] = make_float4(n0, n1, n2, a0);
        o4[1] = make_float4(a1, a2, c0, c1);
        o4[2] = make_float4(c2, o0, o1, o2);
        o4[3] = make_float4(a0 + 1.54f*dx, a1 + 1.54f*dy, a2 + 1.54f*dz, 0.f);
    } else {
        int i = ((blk - 81) * 256 + tid) * 4;
        if (i < 925 * 64) {
            float4 v = *(const float4*)(W + i);
            __half2 h0 = __floats2half2_rn(v.x, v.y);
            __half2 h1 = __floats2half2_rn(v.z, v.w);
            uint2 u;
            u.x = *(unsigned*)&h0;
            u.y = *(unsigned*)&h1;
            *(uint2*)(g_wh + i) = u;
        }
    }
}

// ---------------------------------------------------------------------------
// Main: one CTA per (b,l); 256 threads = 8 autonomous warps, 4 tuples each.
// Only __syncwarp; shuffles warp-uniform. launch_bounds caps regs for 6 CTA/SM.
//   coords5 slot layout: [0..2]=N [3..5]=CA [6..8]=C [9..11]=O [12..14]=CB
// ---------------------------------------------------------------------------
__global__ void __launch_bounds__(256, 6)
k_main(const int* __restrict__ nidx, float* __restrict__ out) {
    __shared__ float s_c5[8][5 * 16];                      // per-warp: 4 nb + self
    __shared__ __align__(16) unsigned s_off[8][4][28];     // byte offsets, 25 used

    const int tid  = threadIdx.x;
    const int lane = tid & 31;
    const int w    = tid >> 5;
    const int bid  = blockIdx.x;          // = b*L + l
    const int b    = bid >> 11;
    const int l    = bid & (LQ - 1);
    const int base = b * LQ;

    // Phase A: indices + coords (warp-local). Shuffles executed by ALL lanes.
    int r4 = bid, relreg = 0;
    if (lane < 4) {
        int nb = nidx[bid * KQ + w * 4 + lane];
        relreg = max(-32, min(32, nb - l)) + 32;
        r4 = base + nb;
    }
    {
        int resid = (lane >> 2) & 7;
        int word  = lane & 3;
        int rsel  = __shfl_sync(0xFFFFFFFFu, r4, resid < 5 ? resid : 4);
        if (lane < 20)
            ((float4*)&s_c5[w][0])[resid * 4 + word] = ((const float4*)g_c5)[rsel * 4 + word];
    }
    __syncwarp();

    // Phase B: 100 distances -> W byte offsets (u32) in warp smem
    int e = c_pair[lane < 25 ? lane : 0];
    int rbase = e & 0xffff;               // p*37
    int a3 = (e >> 16) & 0xff;            // self atom offset
    int q3 = e >> 24;                     // neighbor atom offset
    float sx = s_c5[w][4*16 + a3 + 0];
    float sy = s_c5[w][4*16 + a3 + 1];
    float sz = s_c5[w][4*16 + a3 + 2];
    #pragma unroll
    for (int t = 0; t < 4; t++) {
        float dx = sx - s_c5[w][t*16 + q3 + 0];
        float dy = sy - s_c5[w][t*16 + q3 + 1];
        float dz = sz - s_c5[w][t*16 + q3 + 2];
        float d = sqrt_approx(dx*dx + dy*dy + dz*dz);
        int i = (int)ceilf((d - 2.0f) * 2.0f);   // searchsorted-left, bins 2.0+0.5i
        i = max(0, min(36, i));
        if (lane < 25)
            s_off[w][t][lane] = (unsigned)(rbase + i) << 7;   // row * 128 bytes
    }
    __syncwarp();

    // Phase C: gather-accumulate. 8 lanes per tuple, 8 h each.
    const int t  = lane >> 3;             // tuple within warp
    const int ln = lane & 7;
    const int rel_t = __shfl_sync(0xFFFFFFFFu, relreg, t);

    const float4* __restrict__ P4 = (const float4*)g_petab;
    float4 A0 = P4[rel_t * 16 + 2*ln];
    float4 A1 = P4[rel_t * 16 + 2*ln + 1];

    const unsigned* wp = &s_off[w][t][0];
    const char* __restrict__ Wb = (const char*)g_wh + ln * 16;

    #pragma unroll
    for (int g = 0; g < 3; g++) {         // 3 super-groups of 8 rows, staged 4+4
        uint4 ww = *(const uint4*)&wp[4*g];
        uint4 w2 = *(const uint4*)&wp[4*g + 12];
        uint4 r0 = *(const uint4*)(Wb + ww.x);
        uint4 r1 = *(const uint4*)(Wb + ww.y);
        uint4 r2 = *(const uint4*)(Wb + ww.z);
        uint4 r3 = *(const uint4*)(Wb + ww.w);
        __half2 s0 = __hadd2(__hadd2(H2(r0.x), H2(r1.x)), __hadd2(H2(r2.x), H2(r3.x)));
        __half2 s1 = __hadd2(__hadd2(H2(r0.y), H2(r1.y)), __hadd2(H2(r2.y), H2(r3.y)));
        __half2 s2 = __hadd2(__hadd2(H2(r0.z), H2(r1.z)), __hadd2(H2(r2.z), H2(r3.z)));
        __half2 s3 = __hadd2(__hadd2(H2(r0.w), H2(r1.w)), __hadd2(H2(r2.w), H2(r3.w)));
        uint4 r4a = *(const uint4*)(Wb + w2.x);
        uint4 r5  = *(const uint4*)(Wb + w2.y);
        uint4 r6  = *(const uint4*)(Wb + w2.z);
        uint4 r7  = *(const uint4*)(Wb + w2.w);
        s0 = __hadd2(s0, __hadd2(__hadd2(H2(r4a.x), H2(r5.x)), __hadd2(H2(r6.x), H2(r7.x))));
        s1 = __hadd2(s1, __hadd2(__hadd2(H2(r4a.y), H2(r5.y)), __hadd2(H2(r6.y), H2(r7.y))));
        s2 = __hadd2(s2, __hadd2(__hadd2(H2(r4a.z), H2(r5.z)), __hadd2(H2(r6.z), H2(r7.z))));
        s3 = __hadd2(s3, __hadd2(__hadd2(H2(r4a.w), H2(r5.w)), __hadd2(H2(r6.w), H2(r7.w))));
        float2 f;
        f = __half22float2(s0); A0.x += f.x; A0.y += f.y;
        f = __half22float2(s1); A0.z += f.x; A0.w += f.y;
        f = __half22float2(s2); A1.x += f.x; A1.y += f.y;
        f = __half22float2(s3); A1.z += f.x; A1.w += f.y;
    }
    {   // leftover 25th row: super-group layout uses wp[0..3],[12..15] g=0;
        // [4..7],[16..19] g=1; [8..11],[20..23] g=2 -> leftover is wp[24]
        uint4 ra = *(const uint4*)(Wb + wp[24]);
        float2 f;
        f = __half22float2(H2(ra.x)); A0.x += f.x; A0.y += f.y;
        f = __half22float2(H2(ra.y)); A0.z += f.x; A0.w += f.y;
        f = __half22float2(H2(ra.z)); A1.x += f.x; A1.y += f.y;
        f = __half22float2(H2(ra.w)); A1.z += f.x; A1.w += f.y;
    }

    float4* out4 = (float4*)out + (size_t)bid * 512;
    const int kk = w * 4 + t;
    out4[kk * 16 + 2*ln]     = A0;
    out4[kk * 16 + 2*ln + 1] = A1;
}

// ---------------------------------------------------------------------------
extern "C" void kernel_launch(void* const* d_in, const int* in_sizes, int n_in,
                              void* d_out, int out_size) {
    const float* coords = (const float*)d_in[0];   // (2,2048,4,3) f32
    const int*   nidx   = (const int*)  d_in[1];   // (2,2048,32) i32
    const float* W      = (const float*)d_in[2];   // (989,64) f32
    const float* bvec   = (const float*)d_in[3];   // (64,) f32

    k_prep<<<81 + (925*64/4 + 255)/256, 256>>>(W, bvec, coords);
    k_main<<<NRES, 256>>>(nidx, (float*)d_out);
}

// round 8
// speedup vs baseline: 1.8887x; 1.0794x over previous
#include <cuda_runtime.h>
#include <cuda_fp16.h>
#include <math.h>

#define BQ 2
#define LQ 2048
#define KQ 32
#define NRES (BQ*LQ)

// Scratch (allocation-free rule: __device__ globals)
__device__ __align__(16) float  g_petab[65 * 64];     // pe(rel) @ W_pe + b_edge (fp32)
__device__ __align__(16) __half g_wh[925 * 64];       // W_dist in fp16
__device__ __align__(16) float  g_c5[NRES * 16];      // 5 atoms x 3, padded to 16

// packed pair decode: p*37 | (p/5*3)<<16 | (p%5*3)<<24
#define PAIR(p) ((p)*37 | ((p)/5*3)<<16 | ((p)%5*3)<<24)
__constant__ int c_pair[25] = {
    PAIR(0),  PAIR(1),  PAIR(2),  PAIR(3),  PAIR(4),
    PAIR(5),  PAIR(6),  PAIR(7),  PAIR(8),  PAIR(9),
    PAIR(10), PAIR(11), PAIR(12), PAIR(13), PAIR(14),
    PAIR(15), PAIR(16), PAIR(17), PAIR(18), PAIR(19),
    PAIR(20), PAIR(21), PAIR(22), PAIR(23), PAIR(24)
};

__device__ __forceinline__ float sqrt_approx(float s) {
    float d;
    asm("sqrt.approx.f32 %0, %1;" : "=f"(d) : "f"(s));
    return d;
}
__device__ __forceinline__ __half2 H2(unsigned u) { return *(__half2*)&u; }

// ---------------------------------------------------------------------------
// Prologue (one kernel, independent block ranges):
//   blocks [0,65)  : PE table (MUFU fast-math);  [65,81) : coords5;
//   blocks [81,..) : W fp16 convert
// ---------------------------------------------------------------------------
__global__ void k_prep(const float* __restrict__ W, const float* __restrict__ bvec,
                       const float* __restrict__ coords) {
    int blk = blockIdx.x, tid = threadIdx.x;
    if (blk < 65) {
        if (tid < 64) {
            float rel = (float)(blk - 32);
            const float coef = -0.14391156831212787f;   // -ln(10000)/64
            float acc = bvec[tid];
            #pragma unroll
            for (int j = 0; j < 32; j++) {
                float dt  = __expf((float)(2 * j) * coef);
                float ang = rel * dt;
                acc += __sinf(ang) * W[(925 + 2*j)     * 64 + tid];
                acc += __cosf(ang) * W[(925 + 2*j + 1) * 64 + tid];
            }
            g_petab[blk * 64 + tid] = acc;
        }
    } else if (blk < 81) {
        int r = (blk - 65) * 256 + tid;    // 0..4095
        const float* c = coords + (size_t)r * 12;
        float n0 = c[0], n1 = c[1],  n2 = c[2];
        float a0 = c[3], a1 = c[4],  a2 = c[5];
        float c0 = c[6], c1 = c[7],  c2 = c[8];
        float o0 = c[9], o1 = c[10], o2 = c[11];

        float ux = n0 - a0, uy = n1 - a1, uz = n2 - a2;
        float un = fmaxf(__fsqrt_rn(ux*ux + uy*uy + uz*uz), 1e-12f);
        ux = __fdiv_rn(ux, un); uy = __fdiv_rn(uy, un); uz = __fdiv_rn(uz, un);
        float vx = c0 - a0, vy = c1 - a1, vz = c2 - a2;
        float vn = fmaxf(__fsqrt_rn(vx*vx + vy*vy + vz*vz), 1e-12f);
        vx = __fdiv_rn(vx, vn); vy = __fdiv_rn(vy, vn); vz = __fdiv_rn(vz, vn);
        float bx = ux + vx, by = uy + vy, bz = uz + vz;
        float bn = fmaxf(__fsqrt_rn(bx*bx + by*by + bz*bz), 1e-12f);
        bx = __fdiv_rn(bx, bn); by = __fdiv_rn(by, bn); bz = __fdiv_rn(bz, bn);
        float px = uy*vz - uz*vy;
        float py = uz*vx - ux*vz;
        float pz = ux*vy - uy*vx;
        float pn = fmaxf(__fsqrt_rn(px*px + py*py + pz*pz), 1e-12f);
        px = __fdiv_rn(px, pn); py = __fdiv_rn(py, pn); pz = __fdiv_rn(pz, pn);
        float dx = -bx + 0.5f*px, dy = -by + 0.5f*py, dz = -bz + 0.5f*pz;
        float dn = fmaxf(__fsqrt_rn(dx*dx + dy*dy + dz*dz), 1e-12f);
        dx = __fdiv_rn(dx, dn); dy = __fdiv_rn(dy, dn); dz = __fdiv_rn(dz, dn);

        float4* o4 = (float4*)(g_c5 + (size_t)r * 16);
        o4[0] = make_float4(n0, n1, n2, a0);
        o4[1] = make_float4(a1, a2, c0, c1);
        o4[2] = make_float4(c2, o0, o1, o2);
        o4[3] = make_float4(a0 + 1.54f*dx, a1 + 1.54f*dy, a2 + 1.54f*dz, 0.f);
    } else {
        int i = ((blk - 81) * 256 + tid) * 4;
        if (i < 925 * 64) {
            float4 v = *(const float4*)(W + i);
            __half2 h0 = __floats2half2_rn(v.x, v.y);
            __half2 h1 = __floats2half2_rn(v.z, v.w);
            uint2 u;
            u.x = *(unsigned*)&h0;
            u.y = *(unsigned*)&h1;
            *(uint2*)(g_wh + i) = u;
        }
    }
}

// ---------------------------------------------------------------------------
// Main: one CTA per (b,l); 256 threads = 8 autonomous warps, 4 tuples each.
// Exact R6 structure (best measured k_main: 26.5us). No reg cap.
//   coords5 slot layout: [0..2]=N [3..5]=CA [6..8]=C [9..11]=O [12..14]=CB
// ---------------------------------------------------------------------------
__global__ void __launch_bounds__(256)
k_main(const int* __restrict__ nidx, float* __restrict__ out) {
    __shared__ float s_c5[8][5 * 16];                  // per-warp: 4 nb + self(4)
    __shared__ __align__(16) unsigned short s_rows[8][4][32];  // 25 used per tuple

    const int tid  = threadIdx.x;
    const int lane = tid & 31;
    const int w    = tid >> 5;
    const int bid  = blockIdx.x;          // = b*L + l
    const int b    = bid >> 11;
    const int l    = bid & (LQ - 1);
    const int base = b * LQ;

    // Phase A: indices + coords (warp-local). Shuffles executed by ALL lanes.
    int r4 = bid, relreg = 0;
    if (lane < 4) {
        int nb = nidx[bid * KQ + w * 4 + lane];
        relreg = max(-32, min(32, nb - l)) + 32;
        r4 = base + nb;
    }
    {
        int resid = (lane >> 2) & 7;      // 0..4 for lanes<20
        int word  = lane & 3;
        int rsel  = __shfl_sync(0xFFFFFFFFu, r4, resid < 5 ? resid : 4);
        if (lane < 20)
            ((float4*)&s_c5[w][0])[resid * 4 + word] = ((const float4*)g_c5)[rsel * 4 + word];
    }
    __syncwarp();

    // Phase B: 100 distances -> bin rows (u16) in warp smem
    int e = c_pair[lane < 25 ? lane : 0];
    int rbase = e & 0xffff;               // p*37
    int a3 = (e >> 16) & 0xff;            // self atom offset
    int q3 = e >> 24;                     // neighbor atom offset
    float sx = s_c5[w][4*16 + a3 + 0];
    float sy = s_c5[w][4*16 + a3 + 1];
    float sz = s_c5[w][4*16 + a3 + 2];
    #pragma unroll
    for (int t = 0; t < 4; t++) {
        float dx = sx - s_c5[w][t*16 + q3 + 0];
        float dy = sy - s_c5[w][t*16 + q3 + 1];
        float dz = sz - s_c5[w][t*16 + q3 + 2];
        float d = sqrt_approx(dx*dx + dy*dy + dz*dz);
        int i = (int)ceilf((d - 2.0f) * 2.0f);   // searchsorted-left, bins 2.0+0.5i
        i = max(0, min(36, i));
        if (lane < 25)
            s_rows[w][t][lane] = (unsigned short)(rbase + i);
    }
    __syncwarp();

    // Phase C: gather-accumulate. 8 lanes per tuple, 8 h each.
    const int t  = lane >> 3;             // tuple within warp
    const int ln = lane & 7;
    const int rel_t = __shfl_sync(0xFFFFFFFFu, relreg, t);   // all lanes execute

    const float4* __restrict__ P4 = (const float4*)g_petab;
    float4 A0 = P4[rel_t * 16 + 2*ln];
    float4 A1 = P4[rel_t * 16 + 2*ln + 1];

    const unsigned* wp = (const unsigned*)&s_rows[w][t][0];
    const uint4* __restrict__ Wv = (const uint4*)g_wh;   // 8 uint4 per 64-h row

    #pragma unroll
    for (int g = 0; g < 3; g++) {         // 3 super-groups of 8 rows
        uint4 ww = *(const uint4*)&wp[4*g];
        uint4 r0 = Wv[(ww.x & 0xffffu) * 8 + ln];
        uint4 r1 = Wv[(ww.x >> 16)     * 8 + ln];
        uint4 r2 = Wv[(ww.y & 0xffffu) * 8 + ln];
        uint4 r3 = Wv[(ww.y >> 16)     * 8 + ln];
        __half2 s0 = __hadd2(__hadd2(H2(r0.x), H2(r1.x)), __hadd2(H2(r2.x), H2(r3.x)));
        __half2 s1 = __hadd2(__hadd2(H2(r0.y), H2(r1.y)), __hadd2(H2(r2.y), H2(r3.y)));
        __half2 s2 = __hadd2(__hadd2(H2(r0.z), H2(r1.z)), __hadd2(H2(r2.z), H2(r3.z)));
        __half2 s3 = __hadd2(__hadd2(H2(r0.w), H2(r1.w)), __hadd2(H2(r2.w), H2(r3.w)));
        uint4 r4a = Wv[(ww.z & 0xffffu) * 8 + ln];
        uint4 r5  = Wv[(ww.z >> 16)     * 8 + ln];
        uint4 r6  = Wv[(ww.w & 0xffffu) * 8 + ln];
        uint4 r7  = Wv[(ww.w >> 16)     * 8 + ln];
        s0 = __hadd2(s0, __hadd2(__hadd2(H2(r4a.x), H2(r5.x)), __hadd2(H2(r6.x), H2(r7.x))));
        s1 = __hadd2(s1, __hadd2(__hadd2(H2(r4a.y), H2(r5.y)), __hadd2(H2(r6.y), H2(r7.y))));
        s2 = __hadd2(s2, __hadd2(__hadd2(H2(r4a.z), H2(r5.z)), __hadd2(H2(r6.z), H2(r7.z))));
        s3 = __hadd2(s3, __hadd2(__hadd2(H2(r4a.w), H2(r5.w)), __hadd2(H2(r6.w), H2(r7.w))));
        float2 f;
        f = __half22float2(s0); A0.x += f.x; A0.y += f.y;
        f = __half22float2(s1); A0.z += f.x; A0.w += f.y;
        f = __half22float2(s2); A1.x += f.x; A1.y += f.y;
        f = __half22float2(s3); A1.z += f.x; A1.w += f.y;
    }
    {   // leftover 25th row (u16[24])
        uint4 ra = Wv[(wp[12] & 0xffffu) * 8 + ln];
        float2 f;
        f = __half22float2(H2(ra.x)); A0.x += f.x; A0.y += f.y;
        f = __half22float2(H2(ra.y)); A0.z += f.x; A0.w += f.y;
        f = __half22float2(H2(ra.z)); A1.x += f.x; A1.y += f.y;
        f = __half22float2(H2(ra.w)); A1.z += f.x; A1.w += f.y;
    }

    float4* out4 = (float4*)out + (size_t)bid * 512;
    const int kk = w * 4 + t;
    out4[kk * 16 + 2*ln]     = A0;
    out4[kk * 16 + 2*ln + 1] = A1;
}

// ---------------------------------------------------------------------------
extern "C" void kernel_launch(void* const* d_in, const int* in_sizes, int n_in,
                              void* d_out, int out_size) {
    const float* coords = (const float*)d_in[0];   // (2,2048,4,3) f32
    const int*   nidx   = (const int*)  d_in[1];   // (2,2048,32) i32
    const float* W      = (const float*)d_in[2];   // (989,64) f32
    const float* bvec   = (const float*)d_in[3];   // (64,) f32

    k_prep<<<81 + (925*64/4 + 255)/256, 256>>>(W, bvec, coords);
    k_main<<<NRES, 256>>>(nidx, (float*)d_out);
}